// round 17
// baseline (speedup 1.0000x reference)
#include <cuda_runtime.h>
#include <cuda_fp16.h>
#include <cstdint>

#define BATCH 64
#define NNODE 27
#define CDIM  512
#define NNSQ  729
#define NROWS_X (BATCH*NNODE)      // 1728
#define NROWS_E (BATCH*NNSQ)       // 46656

#define BM 128
#define BN 128
#define BK 64
#define SROWB 144                   // smem row stride bytes (64 halves + 16B pad)
#define ARR_BYTES (128*SROWB)       // 18432
#define STAGE_BYTES (2*ARR_BYTES)   // A | B = 36864
#define NSTAGE 2
#define SMEM_GEMM (NSTAGE*STAGE_BYTES)   // 73728 -> 2 CTAs/SM

#define EDGE_CTAS (365*4)           // 1460
#define NODE_CTAS (14*16)           // 224

// epilogue smem: fp16 sigmoid tile + fp32 Vix/ge/be
#define SSTR2 520                              // halves per row
#define EPI_SIG_BYTES (27*SSTR2*2)             // 28080
#define EPI_VIX_OFF   EPI_SIG_BYTES            // float[512]
#define EPI_GE_OFF    (EPI_VIX_OFF + 2048)
#define EPI_BE_OFF    (EPI_GE_OFF + 2048)
#define EPI_BYTES     (EPI_BE_OFF + 2048)      // 34224 -> 4 CTAs/SM (thread-limited)

// prep kernel block ranges (256 thr each)
#define PREP_E_BLKS (NROWS_E*CDIM/8/256)   // 11664 (2 float4 per thread)
#define PREP_X_BLKS (NROWS_X*CDIM/4/256)   // 864
#define PREP_W_BLKS (16*16*5)              // 1280

// ------------------------------------------------------------------
// scratch (device globals; allocs are forbidden)
// ------------------------------------------------------------------
__device__ __half g_elin[(size_t)NROWS_E*CDIM];         // e_lin fp16
__device__ __half g_node[(size_t)NROWS_X*2048];         // Vix|Vjx|Ujx|XU fp16
__device__ __half g_eA[(size_t)NROWS_E*CDIM];           // edge fp16
__device__ __half g_xA[(size_t)NROWS_X*CDIM];           // x fp16
__device__ __half g_WEt[512*512];                       // WE^T fp16
__device__ __half g_Wct[2048*512];                      // [WA|WB|WV|WU]^T fp16

// ------------------------------------------------------------------
// helpers
// ------------------------------------------------------------------
__device__ __forceinline__ uint32_t smem_to_u32(const void* p) {
    uint32_t a;
    asm("{ .reg .u64 t; cvta.to.shared.u64 t, %1; cvt.u32.u64 %0, t; }" : "=r"(a) : "l"(p));
    return a;
}
__device__ __forceinline__ void cp_async16(uint32_t dst, const void* src, bool pred) {
    int sz = pred ? 16 : 0;
    asm volatile("cp.async.cg.shared.global [%0], [%1], 16, %2;"
                 :: "r"(dst), "l"(src), "r"(sz) : "memory");
}
__device__ __forceinline__ void cp_async16_ca(uint32_t dst, const void* src) {
    asm volatile("cp.async.ca.shared.global [%0], [%1], 16;"
                 :: "r"(dst), "l"(src) : "memory");
}
__device__ __forceinline__ void ldsm4(uint32_t& r0, uint32_t& r1, uint32_t& r2, uint32_t& r3,
                                      uint32_t addr) {
    asm volatile("ldmatrix.sync.aligned.m8n8.x4.shared.b16 {%0,%1,%2,%3}, [%4];"
                 : "=r"(r0), "=r"(r1), "=r"(r2), "=r"(r3) : "r"(addr));
}
__device__ __forceinline__ void mma16816(float* c,
                                         uint32_t a0, uint32_t a1, uint32_t a2, uint32_t a3,
                                         uint32_t b0, uint32_t b1) {
    asm volatile("mma.sync.aligned.m16n8k16.row.col.f32.f16.f16.f32 "
                 "{%0,%1,%2,%3},{%4,%5,%6,%7},{%8,%9},{%0,%1,%2,%3};"
                 : "+f"(c[0]), "+f"(c[1]), "+f"(c[2]), "+f"(c[3])
                 : "r"(a0), "r"(a1), "r"(a2), "r"(a3), "r"(b0), "r"(b1));
}
__device__ __forceinline__ float sigmoid_fast(float x) {
    float t;
    asm("tanh.approx.f32 %0, %1;" : "=f"(t) : "f"(0.5f * x));
    return fmaf(t, 0.5f, 0.5f);
}
__device__ __forceinline__ float exp01(float s) {
    float p = fmaf(s, 0.14285714f, 1.f);
    p = fmaf(p*s, 0.16666667f, 1.f);
    p = fmaf(p*s, 0.2f, 1.f);
    p = fmaf(p*s, 0.25f, 1.f);
    p = fmaf(p*s, 0.33333333f, 1.f);
    p = fmaf(p*s, 0.5f, 1.f);
    return fmaf(p, s, 1.f);
}
__device__ __forceinline__ void st_cs_f4(float* p, float4 v) {
    asm volatile("st.global.cs.v4.f32 [%0], {%1,%2,%3,%4};"
                 :: "l"(p), "f"(v.x), "f"(v.y), "f"(v.z), "f"(v.w) : "memory");
}

// ------------------------------------------------------------------
// K_prep: one launch = edge convert (2xfloat4/thr) | x convert | W^T
// ------------------------------------------------------------------
__global__ void prep_all(const float* __restrict__ edge, const float* __restrict__ x,
                         const float* __restrict__ WE, const float* __restrict__ WA,
                         const float* __restrict__ WB, const float* __restrict__ WV,
                         const float* __restrict__ WU)
{
    int blk = blockIdx.x;
    if (blk < PREP_E_BLKS) {
        int i = (blk*256 + threadIdx.x)*2;
#pragma unroll
        for (int u = 0; u < 2; u++) {
            float4 v = ((const float4*)edge)[i + u];
            ((__half2*)g_eA)[2*(i+u)]   = __floats2half2_rn(v.x, v.y);
            ((__half2*)g_eA)[2*(i+u)+1] = __floats2half2_rn(v.z, v.w);
        }
        return;
    }
    if (blk < PREP_E_BLKS + PREP_X_BLKS) {
        int i = (blk - PREP_E_BLKS)*256 + threadIdx.x;
        float4 v = ((const float4*)x)[i];
        ((__half2*)g_xA)[2*i]   = __floats2half2_rn(v.x, v.y);
        ((__half2*)g_xA)[2*i+1] = __floats2half2_rn(v.z, v.w);
        return;
    }
    __shared__ float tile[32][33];
    int wblk = blk - PREP_E_BLKS - PREP_X_BLKS;
    int z  = wblk / 256;
    int t2 = wblk % 256;
    int bx = t2 & 15, by = t2 >> 4;
    const float* W = (z == 0) ? WE : (z == 1) ? WA : (z == 2) ? WB : (z == 3) ? WV : WU;
    __half* Oh = (z == 0) ? g_WEt : g_Wct;
    const int nOff = (z == 0) ? 0 : (z - 1) * 512;
    const int k0 = bx * 32, n0 = by * 32;
    const int tx = threadIdx.x & 31, ty = threadIdx.x >> 5;
#pragma unroll
    for (int q = 0; q < 4; q++)
        tile[ty + 8*q][tx] = W[(size_t)(k0 + ty + 8*q)*512 + n0 + tx];
    __syncthreads();
#pragma unroll
    for (int q = 0; q < 4; q++)
        Oh[(size_t)(nOff + n0 + ty + 8*q)*512 + k0 + tx] = __float2half_rn(tile[tx][ty + 8*q]);
}

// ------------------------------------------------------------------
// G: combined fp16 GEMM.  256 thr, 8 warps, warp 32x64,
// CTA 128x128, BK=64, 2-stage, 2 CTAs/SM.  B loads via .ca (L1).
// ------------------------------------------------------------------
__device__ __forceinline__ void load_stage(uint32_t s0, int tid, int row0, int n0, int M, int kt,
    const __half* __restrict__ A, const __half* __restrict__ B)
{
#pragma unroll
    for (int q = 0; q < 4; q++) {
        int idx = tid + q*256;
        int r = idx >> 3, c = idx & 7;
        uint32_t doff = (uint32_t)r*SROWB + (uint32_t)c*16;
        int ar = row0 + r;
        bool av = ar < M;
        size_t agoff = (size_t)(av ? ar : 0)*512 + kt + c*8;
        cp_async16(s0 + doff, A + agoff, av);
        size_t bgoff = (size_t)(n0 + r)*512 + kt + c*8;
        cp_async16_ca(s0 + ARR_BYTES + doff, B + bgoff);
    }
    asm volatile("cp.async.commit_group;" ::: "memory");
}

__device__ __forceinline__ void compute_stage(uint32_t s0, int lane, int wm, int wn,
                                              float acc[2][8][4])
{
#pragma unroll
    for (int s = 0; s < 4; s++) {
        uint32_t a[2][4];
#pragma unroll
        for (int f = 0; f < 2; f++) {
            uint32_t ra = s0 + (uint32_t)(wm*32 + f*16 + (lane & 15))*SROWB
                             + (uint32_t)((lane >> 4)*16 + s*32);
            ldsm4(a[f][0], a[f][1], a[f][2], a[f][3], ra);
        }
#pragma unroll
        for (int h = 0; h < 2; h++) {
            uint32_t bh[2][4];
#pragma unroll
            for (int q = 0; q < 2; q++) {
                uint32_t rb = s0 + ARR_BYTES
                    + (uint32_t)(wn*64 + h*32 + q*16 + (lane & 15))*SROWB
                    + (uint32_t)((lane >> 4)*16 + s*32);
                ldsm4(bh[q][0], bh[q][1], bh[q][2], bh[q][3], rb);
            }
#pragma unroll
            for (int f = 0; f < 2; f++)
#pragma unroll
                for (int q = 0; q < 2; q++) {
                    int j = h*4 + q*2;
                    mma16816(acc[f][j],   a[f][0], a[f][1], a[f][2], a[f][3], bh[q][0], bh[q][2]);
                    mma16816(acc[f][j+1], a[f][0], a[f][1], a[f][2], a[f][3], bh[q][1], bh[q][3]);
                }
        }
    }
}

__global__ __launch_bounds__(256, 2)
void gemm_all(const __half* __restrict__ eA, const __half* __restrict__ WEt,
              const __half* __restrict__ xA, const __half* __restrict__ Wct,
              __half* __restrict__ Ce, __half* __restrict__ Cn)
{
    extern __shared__ char smem[];
    const uint32_t sb = smem_to_u32(smem);
    const int tid = threadIdx.x;
    const int lane = tid & 31, wid = tid >> 5;
    const int wm = wid >> 1, wn = wid & 1;

    const bool isEdge = blockIdx.x < EDGE_CTAS;
    const __half *A, *B;
    __half* C; int M, ldC, row0, n0;
    if (isEdge) {
        int bx = blockIdx.x % 365, by = blockIdx.x / 365;
        A = eA; B = WEt; C = Ce; M = NROWS_E; ldC = 512;
        row0 = bx * BM; n0 = by * BN;
    } else {
        int c2 = blockIdx.x - EDGE_CTAS;
        int bx = c2 % 14, by = c2 / 14;
        A = xA; B = Wct; C = Cn; M = NROWS_X; ldC = 2048;
        row0 = bx * BM; n0 = by * BN;
    }

    float acc[2][8][4];
#pragma unroll
    for (int f = 0; f < 2; f++)
#pragma unroll
        for (int j = 0; j < 8; j++)
#pragma unroll
            for (int v = 0; v < 4; v++) acc[f][j][v] = 0.f;

    load_stage(sb, tid, row0, n0, M, 0, A, B);

    const int NT = 512 / BK;   // 8
    for (int t = 0; t < NT; t++) {
        asm volatile("cp.async.wait_group 0;" ::: "memory");
        __syncthreads();
        if (t + 1 < NT)
            load_stage(sb + ((t+1) & 1)*STAGE_BYTES, tid, row0, n0, M, (t+1)*BK, A, B);
        compute_stage(sb + (t & 1)*STAGE_BYTES, lane, wm, wn, acc);
    }

#pragma unroll
    for (int f = 0; f < 2; f++) {
        int rbase = row0 + wm*32 + f*16 + (lane >> 2);
#pragma unroll
        for (int h = 0; h < 2; h++) {
            int r = rbase + h*8;
            if (r < M) {
                __half* dst = C + (size_t)r*ldC + n0 + wn*64 + (lane & 3)*2;
#pragma unroll
                for (int j = 0; j < 8; j++)
                    *(__half2*)&dst[j*8] = __floats2half2_rn(acc[f][j][2*h], acc[f][j][2*h+1]);
            }
        }
    }
}

// ------------------------------------------------------------------
// K_epi: per (b,i) CTA, 512 threads, 33.4 KB smem (4 CTAs/SM).
// No elin staging (direct gmem reads); sigmoid tile in fp16 smem;
// edge_out stores streamed (.cs).  Fused node finalize.
// ------------------------------------------------------------------
__global__ __launch_bounds__(512)
void edge_epilogue(const float* __restrict__ x,
                   const float* __restrict__ ge, const float* __restrict__ be,
                   const float* __restrict__ gv, const float* __restrict__ bv,
                   float* __restrict__ edge_out, float* __restrict__ x_out)
{
    extern __shared__ char smc[];
    __half* sS   = (__half*)smc;                    // [27][520] fp16 sigmoid
    float* sVix = (float*)(smc + EPI_VIX_OFF);
    float* sGe  = (float*)(smc + EPI_GE_OFF);
    float* sBe  = (float*)(smc + EPI_BE_OFF);
    __shared__ float rs[16], rs2[16];
    __shared__ float bmean, brstd;

    const int tid = threadIdx.x;
    const int bi  = blockIdx.x;
    const int b   = bi / NNODE;
    const int i   = bi % NNODE;
    const size_t rowBaseE = (size_t)b*NNSQ + (size_t)i*NNODE;
    const __half* eBase  = g_eA + rowBaseE*CDIM;
    const __half* elBase = g_elin + rowBaseE*CDIM;

    {   // Vix / gamma / beta
        const __half* vix = g_node + (size_t)bi*2048;
        sVix[tid] = __half2float(vix[tid]);
        sGe[tid]  = ge[tid];
        sBe[tid]  = be[tid];
    }
    __syncthreads();

    // Phase A: rows (16 warps over 27 rows); elin read directly from gmem
    const int lane = tid & 31, wrp = tid >> 5;
    for (int r = wrp; r < NNODE; r += 16) {
        const __half* elRow = elBase + (size_t)r*CDIM;
        const __half* vjx = g_node + ((size_t)b*NNODE + r)*2048 + 512;  // Vjx fp16
        float4 v[4]; float s = 0.f, s2 = 0.f;
#pragma unroll
        for (int u = 0; u < 4; u++) {
            int c4 = lane + u*32;                    // float4 index 0..127
            uint2 elr = *(const uint2*)&elRow[4*c4]; // 4 halves
            float2 el0 = __half22float2(*(__half2*)&elr.x);
            float2 el1 = __half22float2(*(__half2*)&elr.y);
            float4 vi = *(const float4*)&sVix[4*c4];
            uint2 vjr = *(const uint2*)&vjx[4*c4];
            float2 vj0 = __half22float2(*(__half2*)&vjr.x);
            float2 vj1 = __half22float2(*(__half2*)&vjr.y);
            float4 t;
            t.x = el0.x + vi.x + vj0.x; t.y = el0.y + vi.y + vj0.y;
            t.z = el1.x + vi.z + vj1.x; t.w = el1.y + vi.w + vj1.y;
            v[u] = t;
            s += (t.x + t.y) + (t.z + t.w);
            s2 += (t.x*t.x + t.y*t.y) + (t.z*t.z + t.w*t.w);
        }
#pragma unroll
        for (int o = 16; o > 0; o >>= 1) {
            s  += __shfl_xor_sync(0xffffffffu, s,  o);
            s2 += __shfl_xor_sync(0xffffffffu, s2, o);
        }
        float mean = s * (1.f/512.f);
        float var  = s2 * (1.f/512.f) - mean*mean;
        float rstd = rsqrtf(var + 1e-5f);
        const __half* eRow = eBase + (size_t)r*CDIM;
        float* oRow = edge_out + (rowBaseE + r)*CDIM;
#pragma unroll
        for (int u = 0; u < 4; u++) {
            int c4 = lane + u*32;
            float4 g = *(const float4*)&sGe[4*c4];
            float4 bb = *(const float4*)&sBe[4*c4];
            uint2 er = *(const uint2*)&eRow[4*c4];
            float2 e0 = __half22float2(*(__half2*)&er.x);
            float2 e1 = __half22float2(*(__half2*)&er.y);
            float ln0 = (v[u].x - mean)*rstd*g.x + bb.x;
            float ln1 = (v[u].y - mean)*rstd*g.y + bb.y;
            float ln2 = (v[u].z - mean)*rstd*g.z + bb.z;
            float ln3 = (v[u].w - mean)*rstd*g.w + bb.w;
            float4 eo = { e0.x + fmaxf(ln0, 0.f), e0.y + fmaxf(ln1, 0.f),
                          e1.x + fmaxf(ln2, 0.f), e1.y + fmaxf(ln3, 0.f) };
            st_cs_f4(&oRow[4*c4], eo);
            __half2 h0 = __floats2half2_rn(sigmoid_fast(eo.x), sigmoid_fast(eo.y));
            __half2 h1 = __floats2half2_rn(sigmoid_fast(eo.z), sigmoid_fast(eo.w));
            uint2 sg = { *(uint32_t*)&h0, *(uint32_t*)&h1 };
            *(uint2*)&sS[r*SSTR2 + 4*c4] = sg;
        }
    }
    __syncthreads();

    // Phase B: one column per thread — softmax over j + gated aggregation
    const int c = tid;
    float aggv;
    {
        float sum = 0.f, a = 0.f;
#pragma unroll
        for (int j = 0; j < NNODE; j++) {
            float sv = __half2float(sS[j*SSTR2 + c]);
            float ex = exp01(sv);
            sum += ex;
            a   += ex * __half2float(g_node[((size_t)b*NNODE + j)*2048 + 1024 + c]);  // Ujx
        }
        aggv = a / (sum * (float)NNODE);
    }

    // Phase C (fused node finalize for row bi)
    {
        float t = __half2float(g_node[(size_t)bi*2048 + 1536 + c]) + aggv;   // XU + agg
        float s = t, s2 = t*t;
#pragma unroll
        for (int o = 16; o > 0; o >>= 1) {
            s  += __shfl_xor_sync(0xffffffffu, s,  o);
            s2 += __shfl_xor_sync(0xffffffffu, s2, o);
        }
        if (lane == 0) { rs[wrp] = s; rs2[wrp] = s2; }
        __syncthreads();
        if (tid == 0) {
            float S = 0.f, S2 = 0.f;
#pragma unroll
            for (int k = 0; k < 16; k++) { S += rs[k]; S2 += rs2[k]; }
            float mean = S * (1.f/512.f);
            float var  = S2 * (1.f/512.f) - mean*mean;
            bmean = mean; brstd = rsqrtf(var + 1e-5f);
        }
        __syncthreads();
        float ln = (t - bmean)*brstd*gv[c] + bv[c];
        x_out[(size_t)bi*CDIM + c] = fmaxf(x[(size_t)bi*CDIM + c] + ln, 0.f);
    }
}

// ------------------------------------------------------------------
extern "C" void kernel_launch(void* const* d_in, const int* in_sizes, int n_in,
                              void* d_out, int out_size)
{
    const float* x    = (const float*)d_in[0];
    const float* edge = (const float*)d_in[1];
    const float* WA   = (const float*)d_in[2];
    const float* WB   = (const float*)d_in[3];
    const float* WE   = (const float*)d_in[4];
    const float* WU   = (const float*)d_in[5];
    const float* WV   = (const float*)d_in[6];
    const float* gv   = (const float*)d_in[7];
    const float* bv   = (const float*)d_in[8];
    const float* ge   = (const float*)d_in[9];
    const float* be   = (const float*)d_in[10];

    float* x_out = (float*)d_out;
    float* e_out = (float*)d_out + (size_t)NROWS_X*CDIM;

    cudaFuncSetAttribute(gemm_all, cudaFuncAttributeMaxDynamicSharedMemorySize, SMEM_GEMM);
    cudaFuncSetAttribute(edge_epilogue, cudaFuncAttributeMaxDynamicSharedMemorySize, EPI_BYTES);

    __half *d_elin, *d_node, *d_eA, *d_xA, *d_WEt, *d_Wct;
    cudaGetSymbolAddress((void**)&d_elin, g_elin);
    cudaGetSymbolAddress((void**)&d_node, g_node);
    cudaGetSymbolAddress((void**)&d_eA, g_eA);
    cudaGetSymbolAddress((void**)&d_xA, g_xA);
    cudaGetSymbolAddress((void**)&d_WEt, g_WEt);
    cudaGetSymbolAddress((void**)&d_Wct, g_Wct);

    prep_all<<<PREP_E_BLKS + PREP_X_BLKS + PREP_W_BLKS, 256>>>(edge, x, WE, WA, WB, WV, WU);

    gemm_all<<<EDGE_CTAS + NODE_CTAS, 256, SMEM_GEMM>>>(
        d_eA, d_WEt, d_xA, d_Wct, d_elin, d_node);

    edge_epilogue<<<BATCH*NNODE, 512, EPI_BYTES>>>(
        x, ge, be, gv, bv, e_out, x_out);
}